// round 6
// baseline (speedup 1.0000x reference)
#include <cuda_runtime.h>
#include <math.h>

// Self-convolution via real-packed shared-memory FFT, radix-8 fused passes,
// float2 smem, scoped sync, table-free twiddles (MUFU sincos + squaring),
// zero-pad exploited in fwd pass1 (upper half of z never written or read).

#define SEQ_L   4096
#define OUT_L   (2 * SEQ_L - 1)     // 8191
#define FFT_M   4096
#define NT      512

#define IDX(a)  ((a) + ((a) >> 4))
#define RE_SZ   (FFT_M + (FFT_M >> 4))          // 4352 complex slots
#define S8      0.70710678118654752440f
#define W_ANG   (-6.28318530717958647692f / (float)FFT_M)

// 2-warp named barrier: threads 64i..64i+63 sync on id 1+i
#define BAR_PAIR(tid) asm volatile("bar.sync %0, 64;" :: "r"(1 + ((tid) >> 6)) : "memory")

__device__ __forceinline__ float2 cmul(float2 a, float2 w) {
    return make_float2(a.x * w.x - a.y * w.y, a.x * w.y + a.y * w.x);
}
__device__ __forceinline__ float2 cmulj(float2 a, float2 w) {  // a * conj(w)
    return make_float2(a.x * w.x + a.y * w.y, a.y * w.x - a.x * w.y);
}
__device__ __forceinline__ float2 cadd(float2 a, float2 b) {
    return make_float2(a.x + b.x, a.y + b.y);
}
__device__ __forceinline__ float2 csub(float2 a, float2 b) {
    return make_float2(a.x - b.x, a.y - b.y);
}
__device__ __forceinline__ float2 twof(int t) {   // exp(i * W_ANG * t)
    float2 w;
    __sincosf(W_ANG * (float)t, &w.y, &w.x);
    return w;
}

extern __shared__ float2 s_z[];

// Stages 2+3 of a radix-8 DIF block (after stage-1 results are in v).
__device__ __forceinline__ void fwd8_s23(float2 v[8], float2 w2, float2 w4) {
    #pragma unroll
    for (int h = 0; h < 8; h += 4) {
        float2 u = csub(v[h + 0], v[h + 2]);
        v[h + 0] = cadd(v[h + 0], v[h + 2]);
        v[h + 2] = cmul(u, w2);
        u = csub(v[h + 1], v[h + 3]);
        v[h + 1] = cadd(v[h + 1], v[h + 3]);
        v[h + 3] = make_float2(u.x * w2.y + u.y * w2.x,
                               u.y * w2.y - u.x * w2.x);   // * (-i*W2)
    }
    #pragma unroll
    for (int h = 0; h < 8; h += 2) {
        const float2 u = csub(v[h], v[h + 1]);
        v[h] = cadd(v[h], v[h + 1]);
        v[h + 1] = cmul(u, w4);
    }
}

__device__ __forceinline__ void fwd8(float2 v[8], float2 w1, float2 w2, float2 w4) {
    const float2 wb = make_float2(S8 * (w1.x + w1.y), S8 * (w1.y - w1.x));
    const float2 wc = make_float2(w1.y, -w1.x);
    const float2 wd = make_float2(-S8 * (w1.x - w1.y), -S8 * (w1.y + w1.x));

    float2 s0 = cadd(v[0], v[4]), d0 = csub(v[0], v[4]);
    float2 s1 = cadd(v[1], v[5]), d1 = csub(v[1], v[5]);
    float2 s2 = cadd(v[2], v[6]), d2 = csub(v[2], v[6]);
    float2 s3 = cadd(v[3], v[7]), d3 = csub(v[3], v[7]);
    v[0] = s0; v[1] = s1; v[2] = s2; v[3] = s3;
    v[4] = cmul(d0, w1);
    v[5] = cmul(d1, wb);
    v[6] = cmul(d2, wc);
    v[7] = cmul(d3, wd);

    fwd8_s23(v, w2, w4);
}

__device__ __forceinline__ void inv8(float2 v[8], float2 w1, float2 w2, float2 w4) {
    #pragma unroll
    for (int h = 0; h < 8; h += 2) {
        const float2 t = cmulj(v[h + 1], w4);
        v[h + 1] = csub(v[h], t);
        v[h]     = cadd(v[h], t);
    }
    #pragma unroll
    for (int h = 0; h < 8; h += 4) {
        float2 t = cmulj(v[h + 2], w2);
        v[h + 2] = csub(v[h], t);
        v[h]     = cadd(v[h], t);
        t = make_float2(v[h + 3].x * w2.y - v[h + 3].y * w2.x,
                        v[h + 3].x * w2.x + v[h + 3].y * w2.y);
        v[h + 3] = csub(v[h + 1], t);
        v[h + 1] = cadd(v[h + 1], t);
    }
    {
        float2 t = cmulj(v[4], w1);
        v[4] = csub(v[0], t);
        v[0] = cadd(v[0], t);

        const float2 c1 = make_float2(S8 * (w1.x + w1.y), S8 * (w1.x - w1.y));
        t = cmul(v[5], c1);
        v[5] = csub(v[1], t);
        v[1] = cadd(v[1], t);

        t = make_float2(v[6].x * w1.y - v[6].y * w1.x,
                        v[6].x * w1.x + v[6].y * w1.y);
        v[6] = csub(v[2], t);
        v[2] = cadd(v[2], t);

        const float2 c3 = make_float2(-S8 * (w1.x - w1.y), S8 * (w1.y + w1.x));
        t = cmul(v[7], c3);
        v[7] = csub(v[3], t);
        v[3] = cadd(v[3], t);
    }
}

__global__ void __launch_bounds__(NT, 1)
conv_self_rfft8t_kernel(const float* __restrict__ x, float* __restrict__ out) {
    float2* z = s_z;

    const int tid = threadIdx.x;
    const int b   = blockIdx.x;

    // ---- Load lower half only (upper half is structural zero) ----
    const float2* xb2 = (const float2*)(x + (size_t)b * SEQ_L);
    #pragma unroll
    for (int k = 0; k < 4; k++) {
        const int m = tid + k * NT;          // < 2048
        z[IDX(m)] = xb2[m];
    }
    // no barrier: pass1 reads exactly these thread-local slots

    // ---- fwd pass1: len=4096; v[k+4] inputs are zero => stage1 degenerates
    {
        float2 v[8];
        #pragma unroll
        for (int k = 0; k < 4; k++) v[k] = z[IDX(tid + k * 512)];

        const float2 w1 = twof(tid);
        const float2 w2 = cmul(w1, w1);
        const float2 w4 = cmul(w2, w2);
        const float2 wb = make_float2(S8 * (w1.x + w1.y), S8 * (w1.y - w1.x));
        const float2 wc = make_float2(w1.y, -w1.x);
        const float2 wd = make_float2(-S8 * (w1.x - w1.y), -S8 * (w1.y + w1.x));

        v[4] = cmul(v[0], w1);
        v[5] = cmul(v[1], wb);
        v[6] = cmul(v[2], wc);
        v[7] = cmul(v[3], wd);
        fwd8_s23(v, w2, w4);

        #pragma unroll
        for (int k = 0; k < 8; k++) z[IDX(tid + k * 512)] = v[k];
    }
    __syncthreads();

    // ---- fwd pass2: len=512 (64-thread groups), st=8
    {
        const int p = tid & 63;
        const int base = ((tid - p) << 3) + p;
        int ix[8];
        #pragma unroll
        for (int k = 0; k < 8; k++) ix[k] = IDX(base + k * 64);
        float2 v[8];
        #pragma unroll
        for (int k = 0; k < 8; k++) v[k] = z[ix[k]];
        const float2 w1 = twof(p * 8);
        const float2 w2 = cmul(w1, w1);
        const float2 w4 = cmul(w2, w2);
        fwd8(v, w1, w2, w4);
        #pragma unroll
        for (int k = 0; k < 8; k++) z[ix[k]] = v[k];
    }
    BAR_PAIR(tid);

    // ---- fwd pass3: len=64 (warp-contained), st=64
    {
        const int p = tid & 7;
        const int base = ((tid - p) << 3) + p;
        int ix[8];
        #pragma unroll
        for (int k = 0; k < 8; k++) ix[k] = IDX(base + k * 8);
        float2 v[8];
        #pragma unroll
        for (int k = 0; k < 8; k++) v[k] = z[ix[k]];
        const float2 w1 = twof(p * 64);
        const float2 w2 = cmul(w1, w1);
        const float2 w4 = cmul(w2, w2);
        fwd8(v, w1, w2, w4);
        #pragma unroll
        for (int k = 0; k < 8; k++) z[ix[k]] = v[k];
    }
    __syncwarp();

    // ---- fwd pass4: len=8, contiguous, twiddles = 1
    {
        const int base = tid << 3;
        int ix[8];
        #pragma unroll
        for (int k = 0; k < 8; k++) ix[k] = IDX(base + k);
        float2 v[8];
        #pragma unroll
        for (int k = 0; k < 8; k++) v[k] = z[ix[k]];
        const float2 one = make_float2(1.f, 0.f);
        fwd8(v, one, one, one);
        #pragma unroll
        for (int k = 0; k < 8; k++) z[ix[k]] = v[k];
    }
    __syncthreads();

    // ---- Middle: untangle + square + repack, scaled by 1/M ----
    const float N_ANG = -6.28318530717958647692f / (float)(2 * FFT_M);
    const float invM = 1.0f / (float)FFT_M;
    #pragma unroll
    for (int m = tid; m < FFT_M / 2; m += NT) {
        if (m == 0) {
            float2 z0 = z[IDX(0)];
            const float P = z0.x + z0.y, Q = z0.x - z0.y;
            const float P2 = P * P, Q2 = Q * Q;
            z[IDX(0)] = make_float2(0.5f * invM * (P2 + Q2),
                                    0.5f * invM * (P2 - Q2));
            float2 z1 = z[IDX(1)];
            z[IDX(1)] = make_float2(invM * (z1.x * z1.x - z1.y * z1.y),
                                    invM * (2.0f * z1.x * z1.y));
        } else {
            const int msb = 1 << (31 - __clz(m));
            const int kb = m + msb;
            const int pb = 6 * msb - 1 - kb;
            const int k  = __brev((unsigned)kb) >> 20;

            float wi, wr;
            __sincosf(N_ANG * (float)k, &wi, &wr);

            const float2 zk = z[IDX(kb)];
            const float2 zm = z[IDX(pb)];

            const float Er = 0.5f * (zk.x + zm.x);
            const float Ei = 0.5f * (zk.y - zm.y);
            const float Or = 0.5f * (zk.y + zm.y);
            const float Oi = 0.5f * (zm.x - zk.x);

            const float WOr = Or * wr - Oi * wi;
            const float WOi = Or * wi + Oi * wr;

            const float Pr = Er + WOr, Pi = Ei + WOi;
            const float Qr = Er - WOr, Qi = Ei - WOi;

            const float P2r = Pr * Pr - Pi * Pi, P2i = 2.0f * Pr * Pi;
            const float Q2r = Qr * Qr - Qi * Qi, Q2i = 2.0f * Qr * Qi;

            const float hm = 0.5f * invM;
            const float Epr = hm * (P2r + Q2r);
            const float Epi = hm * (P2i + Q2i);
            const float Sr  = hm * (P2r - Q2r);
            const float Si  = hm * (P2i - Q2i);
            const float Opr = Sr * wr + Si * wi;
            const float Opi = Si * wr - Sr * wi;

            z[IDX(kb)] = make_float2(Epr - Opi, Epi + Opr);
            z[IDX(pb)] = make_float2(Epr + Opi, Opr - Epi);
        }
    }
    __syncthreads();

    // ---- inv passA: lenBig=8, contiguous, twiddles = 1
    {
        const int base = tid << 3;
        int ix[8];
        #pragma unroll
        for (int k = 0; k < 8; k++) ix[k] = IDX(base + k);
        float2 v[8];
        #pragma unroll
        for (int k = 0; k < 8; k++) v[k] = z[ix[k]];
        const float2 one = make_float2(1.f, 0.f);
        inv8(v, one, one, one);
        #pragma unroll
        for (int k = 0; k < 8; k++) z[ix[k]] = v[k];
    }
    __syncwarp();

    // ---- inv passB: lenBig=64 (warp-contained), st=64
    {
        const int p = tid & 7;
        const int base = ((tid - p) << 3) + p;
        int ix[8];
        #pragma unroll
        for (int k = 0; k < 8; k++) ix[k] = IDX(base + k * 8);
        float2 v[8];
        #pragma unroll
        for (int k = 0; k < 8; k++) v[k] = z[ix[k]];
        const float2 w1 = twof(p * 64);
        const float2 w2 = cmul(w1, w1);
        const float2 w4 = cmul(w2, w2);
        inv8(v, w1, w2, w4);
        #pragma unroll
        for (int k = 0; k < 8; k++) z[ix[k]] = v[k];
    }
    BAR_PAIR(tid);

    // ---- inv passC: lenBig=512 (64-thread groups), st=8
    {
        const int p = tid & 63;
        const int base = ((tid - p) << 3) + p;
        int ix[8];
        #pragma unroll
        for (int k = 0; k < 8; k++) ix[k] = IDX(base + k * 64);
        float2 v[8];
        #pragma unroll
        for (int k = 0; k < 8; k++) v[k] = z[ix[k]];
        const float2 w1 = twof(p * 8);
        const float2 w2 = cmul(w1, w1);
        const float2 w4 = cmul(w2, w2);
        inv8(v, w1, w2, w4);
        #pragma unroll
        for (int k = 0; k < 8; k++) z[ix[k]] = v[k];
    }
    __syncthreads();

    // ---- inv passD: lenBig=4096, thread-local slots (tid + 512k)
    float2 v[8];
    {
        #pragma unroll
        for (int k = 0; k < 8; k++) v[k] = z[IDX(tid + k * 512)];
        const float2 w1 = twof(tid);
        const float2 w2 = cmul(w1, w1);
        const float2 w4 = cmul(w2, w2);
        inv8(v, w1, w2, w4);
    }
    // no barrier: store reads exactly this thread's v[]

    // ---- Store (already scaled). Only tid=511,k=7 can hit the 8191 edge.
    float* ob = out + (size_t)b * OUT_L;
    #pragma unroll
    for (int k = 0; k < 7; k++) {
        const int m = tid + k * 512;
        ob[2 * m]     = v[k].x;
        ob[2 * m + 1] = v[k].y;
    }
    {
        const int m = tid + 7 * 512;
        ob[2 * m] = v[7].x;
        if (tid != 511) ob[2 * m + 1] = v[7].y;
    }
}

extern "C" void kernel_launch(void* const* d_in, const int* in_sizes, int n_in,
                              void* d_out, int out_size) {
    (void)in_sizes; (void)n_in; (void)out_size;
    const float* x = (const float*)d_in[0];
    float* out = (float*)d_out;

    const int smem_bytes = RE_SZ * (int)sizeof(float2);  // ~34 KB
    cudaFuncSetAttribute(conv_self_rfft8t_kernel,
                         cudaFuncAttributeMaxDynamicSharedMemorySize, smem_bytes);

    conv_self_rfft8t_kernel<<<128, NT, smem_bytes>>>(x, out);
}

// round 7
// speedup vs baseline: 1.2399x; 1.2399x over previous
#include <cuda_runtime.h>
#include <math.h>

// Self-convolution via real-packed shared-memory FFT, radix-8 fused passes,
// float2 smem, scoped sync, table-free twiddles, zero-pad-aware pass1, and a
// register-fused center: fwd pass4 + spectral untangle/square/repack + inv
// passA all happen in registers on mirrored octet pairs (no smem in between).

#define SEQ_L   4096
#define OUT_L   (2 * SEQ_L - 1)     // 8191
#define FFT_M   4096
#define NT      512

#define IDX(a)  ((a) + (((a) >> 4) << 1))       // pad 2 slots per 16 (keeps 16B align)
#define RE_SZ   (FFT_M + ((FFT_M >> 4) << 1))   // 4608 complex slots (36 KB)
#define S8      0.70710678118654752440f
#define W_ANG   (-6.28318530717958647692f / (float)FFT_M)
#define N_ANG   (-6.28318530717958647692f / (float)(2 * FFT_M))

// 2-warp named barrier: threads 64i..64i+63 sync on id 1+i
#define BAR_PAIR(tid) asm volatile("bar.sync %0, 64;" :: "r"(1 + ((tid) >> 6)) : "memory")

__device__ __forceinline__ float2 cmul(float2 a, float2 w) {
    return make_float2(a.x * w.x - a.y * w.y, a.x * w.y + a.y * w.x);
}
__device__ __forceinline__ float2 cmulj(float2 a, float2 w) {  // a * conj(w)
    return make_float2(a.x * w.x + a.y * w.y, a.y * w.x - a.x * w.y);
}
__device__ __forceinline__ float2 cadd(float2 a, float2 b) {
    return make_float2(a.x + b.x, a.y + b.y);
}
__device__ __forceinline__ float2 csub(float2 a, float2 b) {
    return make_float2(a.x - b.x, a.y - b.y);
}
__device__ __forceinline__ float2 twof(int t) {   // exp(i * W_ANG * t)
    float2 w;
    __sincosf(W_ANG * (float)t, &w.y, &w.x);
    return w;
}

extern __shared__ float2 s_z[];

__device__ __forceinline__ void fwd8_s23(float2 v[8], float2 w2, float2 w4) {
    #pragma unroll
    for (int h = 0; h < 8; h += 4) {
        float2 u = csub(v[h + 0], v[h + 2]);
        v[h + 0] = cadd(v[h + 0], v[h + 2]);
        v[h + 2] = cmul(u, w2);
        u = csub(v[h + 1], v[h + 3]);
        v[h + 1] = cadd(v[h + 1], v[h + 3]);
        v[h + 3] = make_float2(u.x * w2.y + u.y * w2.x,
                               u.y * w2.y - u.x * w2.x);   // * (-i*W2)
    }
    #pragma unroll
    for (int h = 0; h < 8; h += 2) {
        const float2 u = csub(v[h], v[h + 1]);
        v[h] = cadd(v[h], v[h + 1]);
        v[h + 1] = cmul(u, w4);
    }
}

__device__ __forceinline__ void fwd8(float2 v[8], float2 w1, float2 w2, float2 w4) {
    const float2 wb = make_float2(S8 * (w1.x + w1.y), S8 * (w1.y - w1.x));
    const float2 wc = make_float2(w1.y, -w1.x);
    const float2 wd = make_float2(-S8 * (w1.x - w1.y), -S8 * (w1.y + w1.x));

    float2 s0 = cadd(v[0], v[4]), d0 = csub(v[0], v[4]);
    float2 s1 = cadd(v[1], v[5]), d1 = csub(v[1], v[5]);
    float2 s2 = cadd(v[2], v[6]), d2 = csub(v[2], v[6]);
    float2 s3 = cadd(v[3], v[7]), d3 = csub(v[3], v[7]);
    v[0] = s0; v[1] = s1; v[2] = s2; v[3] = s3;
    v[4] = cmul(d0, w1);
    v[5] = cmul(d1, wb);
    v[6] = cmul(d2, wc);
    v[7] = cmul(d3, wd);

    fwd8_s23(v, w2, w4);
}

__device__ __forceinline__ void inv8(float2 v[8], float2 w1, float2 w2, float2 w4) {
    #pragma unroll
    for (int h = 0; h < 8; h += 2) {
        const float2 t = cmulj(v[h + 1], w4);
        v[h + 1] = csub(v[h], t);
        v[h]     = cadd(v[h], t);
    }
    #pragma unroll
    for (int h = 0; h < 8; h += 4) {
        float2 t = cmulj(v[h + 2], w2);
        v[h + 2] = csub(v[h], t);
        v[h]     = cadd(v[h], t);
        t = make_float2(v[h + 3].x * w2.y - v[h + 3].y * w2.x,
                        v[h + 3].x * w2.x + v[h + 3].y * w2.y);
        v[h + 3] = csub(v[h + 1], t);
        v[h + 1] = cadd(v[h + 1], t);
    }
    {
        float2 t = cmulj(v[4], w1);
        v[4] = csub(v[0], t);
        v[0] = cadd(v[0], t);

        const float2 c1 = make_float2(S8 * (w1.x + w1.y), S8 * (w1.x - w1.y));
        t = cmul(v[5], c1);
        v[5] = csub(v[1], t);
        v[1] = cadd(v[1], t);

        t = make_float2(v[6].x * w1.y - v[6].y * w1.x,
                        v[6].x * w1.x + v[6].y * w1.y);
        v[6] = csub(v[2], t);
        v[2] = cadd(v[2], t);

        const float2 c3 = make_float2(-S8 * (w1.x - w1.y), S8 * (w1.y + w1.x));
        t = cmul(v[7], c3);
        v[7] = csub(v[3], t);
        v[3] = cadd(v[3], t);
    }
}

// Untangle X (from packed Z), square, repack Zi — one (kb, pb) mirror pair.
// zk = Z at bitrev slot kb (lower half of its block); zm = mirror slot. hm = 0.5/M.
__device__ __forceinline__ void midpair(float2& zk, float2& zm, int kb, float hm) {
    const int k = __brev((unsigned)kb) >> 20;      // natural frequency index
    float wi, wr;
    __sincosf(N_ANG * (float)k, &wi, &wr);

    const float Er = 0.5f * (zk.x + zm.x);
    const float Ei = 0.5f * (zk.y - zm.y);
    const float Or = 0.5f * (zk.y + zm.y);
    const float Oi = 0.5f * (zm.x - zk.x);

    const float WOr = Or * wr - Oi * wi;
    const float WOi = Or * wi + Oi * wr;

    const float Pr = Er + WOr, Pi = Ei + WOi;
    const float Qr = Er - WOr, Qi = Ei - WOi;

    const float P2r = Pr * Pr - Pi * Pi, P2i = 2.0f * Pr * Pi;
    const float Q2r = Qr * Qr - Qi * Qi, Q2i = 2.0f * Qr * Qi;

    const float Epr = hm * (P2r + Q2r);
    const float Epi = hm * (P2i + Q2i);
    const float Sr  = hm * (P2r - Q2r);
    const float Si  = hm * (P2i - Q2i);
    const float Opr = Sr * wr + Si * wi;
    const float Opi = Si * wr - Sr * wi;

    zk = make_float2(Epr - Opi, Epi + Opr);
    zm = make_float2(Epr + Opi, Opr - Epi);
}

__global__ void __launch_bounds__(NT, 1)
conv_self_rfft8m_kernel(const float* __restrict__ x, float* __restrict__ out) {
    float2* z = s_z;

    const int tid = threadIdx.x;
    const int b   = blockIdx.x;

    // ---- Load lower half only (upper half is structural zero) ----
    const float2* xb2 = (const float2*)(x + (size_t)b * SEQ_L);
    #pragma unroll
    for (int k = 0; k < 4; k++) {
        const int m = tid + k * NT;          // < 2048
        z[IDX(m)] = xb2[m];
    }
    // no barrier: pass1 reads exactly these thread-local slots

    // ---- fwd pass1: len=4096; upper inputs zero => stage1 degenerates
    {
        float2 v[8];
        #pragma unroll
        for (int k = 0; k < 4; k++) v[k] = z[IDX(tid + k * 512)];

        const float2 w1 = twof(tid);
        const float2 w2 = cmul(w1, w1);
        const float2 w4 = cmul(w2, w2);
        const float2 wb = make_float2(S8 * (w1.x + w1.y), S8 * (w1.y - w1.x));
        const float2 wc = make_float2(w1.y, -w1.x);
        const float2 wd = make_float2(-S8 * (w1.x - w1.y), -S8 * (w1.y + w1.x));

        v[4] = cmul(v[0], w1);
        v[5] = cmul(v[1], wb);
        v[6] = cmul(v[2], wc);
        v[7] = cmul(v[3], wd);
        fwd8_s23(v, w2, w4);

        #pragma unroll
        for (int k = 0; k < 8; k++) z[IDX(tid + k * 512)] = v[k];
    }
    __syncthreads();

    // ---- fwd pass2: len=512 (64-thread groups), st=8
    {
        const int p = tid & 63;
        const int base = ((tid - p) << 3) + p;
        int ix[8];
        #pragma unroll
        for (int k = 0; k < 8; k++) ix[k] = IDX(base + k * 64);
        float2 v[8];
        #pragma unroll
        for (int k = 0; k < 8; k++) v[k] = z[ix[k]];
        const float2 w1 = twof(p * 8);
        const float2 w2 = cmul(w1, w1);
        const float2 w4 = cmul(w2, w2);
        fwd8(v, w1, w2, w4);
        #pragma unroll
        for (int k = 0; k < 8; k++) z[ix[k]] = v[k];
    }
    BAR_PAIR(tid);

    // ---- fwd pass3: len=64 (warp-contained), st=64
    {
        const int p = tid & 7;
        const int base = ((tid - p) << 3) + p;
        int ix[8];
        #pragma unroll
        for (int k = 0; k < 8; k++) ix[k] = IDX(base + k * 8);
        float2 v[8];
        #pragma unroll
        for (int k = 0; k < 8; k++) v[k] = z[ix[k]];
        const float2 w1 = twof(p * 64);
        const float2 w2 = cmul(w1, w1);
        const float2 w4 = cmul(w2, w2);
        fwd8(v, w1, w2, w4);
        #pragma unroll
        for (int k = 0; k < 8; k++) z[ix[k]] = v[k];
    }
    __syncthreads();   // merged section reads octets across warps

    // ---- Register-fused center: fwd pass4 + middle + inv passA on mirrored
    //      octet pairs. Octet o = slots [8o, 8o+8). For block [O, 2O) of
    //      octets (O = 2^j), mirror(o) = 3O-1-o; pairing inside: r <-> 7-r.
    if (tid < 256) {
        int oa, oc;
        if (tid == 0) { oa = 0; oc = 1; }     // special octets {0,1}
        else {
            const int msbu = 1 << (31 - __clz(tid));
            const int O = msbu << 1;
            oa = O + (tid - msbu);            // in [O, 1.5O)  -> kb side
            oc = 3 * O - 1 - oa;              // in [1.5O, 2O) -> pb side
        }

        // load both octets as float4 (octets never cross a 16-slot pad block)
        float2 a[8], c[8];
        {
            const float4* pa = (const float4*)&z[IDX(8 * oa)];
            const float4* pc = (const float4*)&z[IDX(8 * oc)];
            #pragma unroll
            for (int i = 0; i < 4; i++) {
                float4 va = pa[i], vc = pc[i];
                a[2 * i]     = make_float2(va.x, va.y);
                a[2 * i + 1] = make_float2(va.z, va.w);
                c[2 * i]     = make_float2(vc.x, vc.y);
                c[2 * i + 1] = make_float2(vc.z, vc.w);
            }
        }

        // fwd pass4: len=8, twiddles = 1
        const float2 one = make_float2(1.f, 0.f);
        fwd8(a, one, one, one);
        fwd8(c, one, one, one);

        // middle
        const float hm = 0.5f / (float)FFT_M;
        if (tid == 0) {
            // slots 0,1: DC/Nyquist of X and the self-paired k=M/2 bin
            {
                const float P = a[0].x + a[0].y, Q = a[0].x - a[0].y;
                const float P2 = P * P, Q2 = Q * Q;
                a[0] = make_float2(hm * (P2 + Q2), hm * (P2 - Q2));
                a[1] = make_float2(2.0f * hm * (a[1].x * a[1].x - a[1].y * a[1].y),
                                   2.0f * hm * (2.0f * a[1].x * a[1].y));
            }
            // block g=1: (2,3); g=2: (4,7),(5,6); g=3: (8,15)..(11,12)
            midpair(a[2], a[3], 2, hm);
            midpair(a[4], a[7], 4, hm);
            midpair(a[5], a[6], 5, hm);
            midpair(c[0], c[7], 8, hm);
            midpair(c[1], c[6], 9, hm);
            midpair(c[2], c[5], 10, hm);
            midpair(c[3], c[4], 11, hm);
        } else {
            const int kb0 = 8 * oa;
            #pragma unroll
            for (int r = 0; r < 8; r++)
                midpair(a[r], c[7 - r], kb0 + r, hm);
        }

        // inv passA: lenBig=8, twiddles = 1
        inv8(a, one, one, one);
        inv8(c, one, one, one);

        // store both octets as float4
        {
            float4* pa = (float4*)&z[IDX(8 * oa)];
            float4* pc = (float4*)&z[IDX(8 * oc)];
            #pragma unroll
            for (int i = 0; i < 4; i++) {
                pa[i] = make_float4(a[2 * i].x, a[2 * i].y,
                                    a[2 * i + 1].x, a[2 * i + 1].y);
                pc[i] = make_float4(c[2 * i].x, c[2 * i].y,
                                    c[2 * i + 1].x, c[2 * i + 1].y);
            }
        }
    }
    __syncthreads();

    // ---- inv passB: lenBig=64 (warp-contained), st=64
    {
        const int p = tid & 7;
        const int base = ((tid - p) << 3) + p;
        int ix[8];
        #pragma unroll
        for (int k = 0; k < 8; k++) ix[k] = IDX(base + k * 8);
        float2 v[8];
        #pragma unroll
        for (int k = 0; k < 8; k++) v[k] = z[ix[k]];
        const float2 w1 = twof(p * 64);
        const float2 w2 = cmul(w1, w1);
        const float2 w4 = cmul(w2, w2);
        inv8(v, w1, w2, w4);
        #pragma unroll
        for (int k = 0; k < 8; k++) z[ix[k]] = v[k];
    }
    BAR_PAIR(tid);

    // ---- inv passC: lenBig=512 (64-thread groups), st=8
    {
        const int p = tid & 63;
        const int base = ((tid - p) << 3) + p;
        int ix[8];
        #pragma unroll
        for (int k = 0; k < 8; k++) ix[k] = IDX(base + k * 64);
        float2 v[8];
        #pragma unroll
        for (int k = 0; k < 8; k++) v[k] = z[ix[k]];
        const float2 w1 = twof(p * 8);
        const float2 w2 = cmul(w1, w1);
        const float2 w4 = cmul(w2, w2);
        inv8(v, w1, w2, w4);
        #pragma unroll
        for (int k = 0; k < 8; k++) z[ix[k]] = v[k];
    }
    __syncthreads();

    // ---- inv passD: lenBig=4096, thread-local slots (tid + 512k)
    float2 v[8];
    {
        #pragma unroll
        for (int k = 0; k < 8; k++) v[k] = z[IDX(tid + k * 512)];
        const float2 w1 = twof(tid);
        const float2 w2 = cmul(w1, w1);
        const float2 w4 = cmul(w2, w2);
        inv8(v, w1, w2, w4);
    }
    // no barrier: store reads exactly this thread's v[]

    // ---- Store (already scaled). Only tid=511,k=7 can hit the 8191 edge.
    float* ob = out + (size_t)b * OUT_L;
    #pragma unroll
    for (int k = 0; k < 7; k++) {
        const int m = tid + k * 512;
        ob[2 * m]     = v[k].x;
        ob[2 * m + 1] = v[k].y;
    }
    {
        const int m = tid + 7 * 512;
        ob[2 * m] = v[7].x;
        if (tid != 511) ob[2 * m + 1] = v[7].y;
    }
}

extern "C" void kernel_launch(void* const* d_in, const int* in_sizes, int n_in,
                              void* d_out, int out_size) {
    (void)in_sizes; (void)n_in; (void)out_size;
    const float* x = (const float*)d_in[0];
    float* out = (float*)d_out;

    const int smem_bytes = RE_SZ * (int)sizeof(float2);  // 36 KB
    cudaFuncSetAttribute(conv_self_rfft8m_kernel,
                         cudaFuncAttributeMaxDynamicSharedMemorySize, smem_bytes);

    conv_self_rfft8m_kernel<<<128, NT, smem_bytes>>>(x, out);
}